// round 13
// baseline (speedup 1.0000x reference)
#include <cuda_runtime.h>
#include <cuda_fp16.h>
#include <cstdint>
#include <cstddef>

#define NN 100000
#define EE 1600000
#define TT (EE + NN)

// ---------------- scratch (static device globals; no allocation) ----------------
__device__ float    g_h[(size_t)NN * 96];    // h fp32 (gemm out, scores in)
__device__ unsigned g_h16[(size_t)NN * 48];  // h fp16 (half2-packed, agg gather payload)
__device__ float    g_out[(size_t)NN * 96];  // agg output (fp32, feeds flat thirds)
__device__ float    g_small[(size_t)NN * 32];// thirds1 out / gemm2 in
__device__ float    g_es[NN];
__device__ float    g_ed[NN];
__device__ int      g_deg[NN];
__device__ int      g_rowptr[NN + 1];
__device__ int      g_cursor[NN];
__device__ int      g_csr[TT];
__device__ int      g_bsum[1024];
__device__ int      g_is64;

// ---------------- f32x2 / cp.async helpers ----------------
__device__ __forceinline__ unsigned long long pack_dup(float a) {
    unsigned long long r;
    unsigned ai = __float_as_uint(a);
    asm("mov.b64 %0, {%1, %1};" : "=l"(r) : "r"(ai));
    return r;
}
__device__ __forceinline__ void fma2(unsigned long long& d, unsigned long long a,
                                     unsigned long long b) {
    asm("fma.rn.f32x2 %0, %1, %2, %0;" : "+l"(d) : "l"(a), "l"(b));
}
__device__ __forceinline__ float2 unpack2(unsigned long long u) {
    float2 f;
    asm("mov.b64 {%0, %1}, %2;" : "=f"(f.x), "=f"(f.y) : "l"(u));
    return f;
}
__device__ __forceinline__ void cp16(void* smem_dst, const void* gsrc, int valid_bytes) {
    unsigned sm = (unsigned)__cvta_generic_to_shared(smem_dst);
    asm volatile("cp.async.cg.shared.global [%0], [%1], 16, %2;"
                 :: "r"(sm), "l"(gsrc), "r"(valid_bytes));
}
__device__ __forceinline__ void cp_commit() {
    asm volatile("cp.async.commit_group;" ::: "memory");
}
__device__ __forceinline__ void cp_wait1() {
    asm volatile("cp.async.wait_group 1;" ::: "memory");
}
__device__ __forceinline__ void cp_wait0() {
    asm volatile("cp.async.wait_group 0;" ::: "memory");
}

// ---------------- edge-index dtype probe ----------------
__global__ void k_probe(const int* __restrict__ ei32) {
    if (threadIdx.x == 0 && blockIdx.x == 0) {
        int acc = 0;
        #pragma unroll 8
        for (int i = 1; i < 512; i += 2) acc |= ei32[i];
        g_is64 = (acc == 0) ? 1 : 0;
    }
}

__device__ __forceinline__ int load_idx(const void* ei, size_t i, int is64, int N) {
    int v = is64 ? (int)((const long long*)ei)[i] : ((const int*)ei)[i];
    v = v < 0 ? 0 : v;
    return v >= N ? N - 1 : v;
}

// ---------------- CSR construction ----------------
__global__ void k_init_deg(int N) {
    int i = blockIdx.x * blockDim.x + threadIdx.x;
    if (i < N) g_deg[i] = 1;  // self-loop
}

__global__ void k_count(const void* __restrict__ ei, int E, int N) {
    int i = blockIdx.x * blockDim.x + threadIdx.x;
    if (i < E) {
        int d = load_idx(ei, (size_t)E + i, g_is64, N);
        atomicAdd(&g_deg[d], 1);
    }
}

__global__ void k_scan_blocks(int N) {
    __shared__ int ws[32];
    int i = blockIdx.x * 1024 + threadIdx.x;
    int v = (i < N) ? g_deg[i] : 0;
    int x = v;
    int lane = threadIdx.x & 31, wid = threadIdx.x >> 5;
    #pragma unroll
    for (int o = 1; o < 32; o <<= 1) {
        int y = __shfl_up_sync(0xffffffffu, x, o);
        if (lane >= o) x += y;
    }
    if (lane == 31) ws[wid] = x;
    __syncthreads();
    if (wid == 0) {
        int w = ws[lane];
        #pragma unroll
        for (int o = 1; o < 32; o <<= 1) {
            int y = __shfl_up_sync(0xffffffffu, w, o);
            if (lane >= o) w += y;
        }
        ws[lane] = w;
    }
    __syncthreads();
    int excl = x - v + (wid ? ws[wid - 1] : 0);
    if (i < N) g_rowptr[i] = excl;
    if (threadIdx.x == 1023) g_bsum[blockIdx.x] = ws[31];
}

__global__ void k_scan_sums(int G, int N) {
    __shared__ int ws[32];
    int tid = threadIdx.x;
    int v = (tid < G) ? g_bsum[tid] : 0;
    int x = v;
    int lane = tid & 31, wid = tid >> 5;
    #pragma unroll
    for (int o = 1; o < 32; o <<= 1) {
        int y = __shfl_up_sync(0xffffffffu, x, o);
        if (lane >= o) x += y;
    }
    if (lane == 31) ws[wid] = x;
    __syncthreads();
    if (wid == 0) {
        int w = ws[lane];
        #pragma unroll
        for (int o = 1; o < 32; o <<= 1) {
            int y = __shfl_up_sync(0xffffffffu, w, o);
            if (lane >= o) w += y;
        }
        ws[lane] = w;
    }
    __syncthreads();
    int excl = x - v + (wid ? ws[wid - 1] : 0);
    if (tid < G) g_bsum[tid] = excl;
    if (tid == 1023) g_rowptr[N] = ws[31];
}

__global__ void k_scan_add(int N) {
    int i = blockIdx.x * blockDim.x + threadIdx.x;
    if (i < N) {
        int v = g_rowptr[i] + g_bsum[i >> 10];
        g_rowptr[i] = v;
        g_cursor[i] = v;
    }
}

__global__ void k_fill(const void* __restrict__ ei, int E, int N) {
    int i = blockIdx.x * blockDim.x + threadIdx.x;
    int tot = E + N;
    if (i >= tot) return;
    int s, d;
    if (i < E) {
        int is64 = g_is64;
        s = load_idx(ei, i, is64, N);
        d = load_idx(ei, (size_t)E + i, is64, N);
    } else {
        s = i - E;
        d = s;
    }
    int pos = atomicAdd(&g_cursor[d], 1);
    if (pos < TT) g_csr[pos] = s;
}

// ---------------- GEMM: C[N,96] = A[N,K] @ W[K,96], f32x2, 3-buffer cp.async ----------
// Also emits fp16 copy of C into h16 (half2-packed) for the agg gather.
template <int K>
__global__ __launch_bounds__(384, 2)
void k_gemm96(const float* __restrict__ A, const float* __restrict__ W,
              float* __restrict__ C, uint4* __restrict__ h16, int N) {
    constexpr int KC = 16;
    constexpr int NCH = K / KC;
    __shared__ float As[3][128][KC + 4];
    __shared__ float Ws[3][KC][96];
    int tid = threadIdx.x;
    int row0 = blockIdx.x * 128;
    int qp = tid % 12;  // cols qp*8 .. qp*8+7
    int rg = tid / 12;  // rows rg*4 .. rg*4+3

    auto stage = [&](int c, int buf) {
        for (int i = tid; i < KC * 24; i += 384) {
            int k = i / 24, q = i % 24;
            cp16(&Ws[buf][k][q * 4], W + (size_t)(c * KC + k) * 96 + q * 4, 16);
        }
        for (int i = tid; i < 128 * (KC / 4); i += 384) {
            int r = i / (KC / 4), kq = i % (KC / 4);
            bool ok = (row0 + r) < N;
            const float* src = A + (ok ? ((size_t)(row0 + r) * K + c * KC + kq * 4) : 0);
            cp16(&As[buf][r][kq * 4], src, ok ? 16 : 0);
        }
    };

    unsigned long long acc[4][4];
    #pragma unroll
    for (int i = 0; i < 4; ++i)
        #pragma unroll
        for (int j = 0; j < 4; ++j) acc[i][j] = 0ull;

    stage(0, 0);
    cp_commit();
    if (NCH > 1) { stage(1, 1); cp_commit(); }

    #pragma unroll
    for (int c = 0; c < NCH; ++c) {
        if (c + 1 < NCH) cp_wait1(); else cp_wait0();
        __syncthreads();
        if (c + 2 < NCH) { stage(c + 2, (c + 2) % 3); cp_commit(); }

        int buf = c % 3;
        #pragma unroll
        for (int k = 0; k < KC; k += 2) {
            float2 a01[4];
            #pragma unroll
            for (int i = 0; i < 4; ++i)
                a01[i] = *reinterpret_cast<const float2*>(&As[buf][rg * 4 + i][k]);
            #pragma unroll
            for (int kk = 0; kk < 2; ++kk) {
                ulonglong2 w01 =
                    *reinterpret_cast<const ulonglong2*>(&Ws[buf][k + kk][qp * 8]);
                ulonglong2 w23 =
                    *reinterpret_cast<const ulonglong2*>(&Ws[buf][k + kk][qp * 8 + 4]);
                #pragma unroll
                for (int i = 0; i < 4; ++i) {
                    unsigned long long a2 = pack_dup(kk ? a01[i].y : a01[i].x);
                    fma2(acc[i][0], a2, w01.x);
                    fma2(acc[i][1], a2, w01.y);
                    fma2(acc[i][2], a2, w23.x);
                    fma2(acc[i][3], a2, w23.y);
                }
            }
        }
    }

    #pragma unroll
    for (int i = 0; i < 4; ++i) {
        int r = row0 + rg * 4 + i;
        if (r < N) {
            ulonglong2 u0, u1;
            u0.x = acc[i][0]; u0.y = acc[i][1];
            u1.x = acc[i][2]; u1.y = acc[i][3];
            *reinterpret_cast<ulonglong2*>(&C[(size_t)r * 96 + qp * 8]) = u0;
            *reinterpret_cast<ulonglong2*>(&C[(size_t)r * 96 + qp * 8 + 4]) = u1;
            // fp16 copy: 8 cols -> 4 half2 -> one uint4 at row*12 + qp
            uint4 hv;
            unsigned* hp = &hv.x;
            #pragma unroll
            for (int j = 0; j < 4; ++j) {
                float2 f = unpack2(acc[i][j]);
                __half2 h2 = __floats2half2_rn(f.x, f.y);
                hp[j] = *reinterpret_cast<unsigned*>(&h2);
            }
            h16[(size_t)r * 12 + qp] = hv;
        }
    }
}

// ---------------- attention scores: es = h@a_s, ed = h@a_d (fp32 h) ----------------
__global__ void k_scores(const float* __restrict__ h, const float* __restrict__ as_,
                         const float* __restrict__ ad_, int N) {
    int gw = (blockIdx.x * blockDim.x + threadIdx.x) >> 5;
    if (gw >= N) return;
    int lane = threadIdx.x & 31;
    const float* hr = h + (size_t)gw * 96;
    float s = 0.f, d = 0.f;
    #pragma unroll
    for (int f = 0; f < 3; ++f) {
        float hv = hr[lane + 32 * f];
        s = fmaf(hv, __ldg(&as_[lane + 32 * f]), s);
        d = fmaf(hv, __ldg(&ad_[lane + 32 * f]), d);
    }
    #pragma unroll
    for (int o = 16; o; o >>= 1) {
        s += __shfl_xor_sync(0xffffffffu, s, o);
        d += __shfl_xor_sync(0xffffffffu, d, o);
    }
    if (lane == 0) { g_es[gw] = s; g_ed[gw] = d; }
}

// ---------------- warp-per-node softmax aggregation, fp16 gather payload -----------
// Softmax weights fp32 (shift-invariant, no max pass). Payload h16: 192B/row.
// Two edges per step: lanes 0..11 -> edge k, lanes 12..23 -> edge k+1.
// Lane (l%12) covers cols 8*(l%12) .. +7, fp32 accumulate; halves combined by shfl.
__global__ void k_agg(const uint4* __restrict__ h16, const float* __restrict__ bias,
                      float* __restrict__ outp, int N) {
    int gw = (blockIdx.x * blockDim.x + threadIdx.x) >> 5;
    if (gw >= N) return;
    int lane = threadIdx.x & 31;
    int beg = g_rowptr[gw], end = g_rowptr[gw + 1];
    float edn = g_ed[gw];
    int half = (lane >= 12) ? 1 : 0;
    int cg = lane % 12;

    float a0 = 0.f, a1 = 0.f, a2 = 0.f, a3 = 0.f;
    float a4 = 0.f, a5 = 0.f, a6 = 0.f, a7 = 0.f;
    float psum = 0.f;

    for (int j0 = beg; j0 < end; j0 += 32) {
        int j = j0 + lane;
        int s = 0;
        float p = 0.f;
        if (j < end) {
            s = __ldg(&g_csr[j]);
            float e = __ldg(&g_es[s]) + edn;
            e = (e > 0.f) ? e : 0.2f * e;
            p = __expf(e);
        }
        psum += p;
        int cnt = min(32, end - j0);
        int k = 0;
        #pragma unroll 4
        for (; k + 1 < cnt; k += 2) {
            int idx = k + half;
            float pk = __shfl_sync(0xffffffffu, p, idx);
            int sk = __shfl_sync(0xffffffffu, s, idx);
            if (lane < 24) {
                uint4 hv = __ldg(h16 + (size_t)sk * 12 + cg);
                const __half2* hh = reinterpret_cast<const __half2*>(&hv);
                float2 f0 = __half22float2(hh[0]);
                float2 f1 = __half22float2(hh[1]);
                float2 f2 = __half22float2(hh[2]);
                float2 f3 = __half22float2(hh[3]);
                a0 = fmaf(pk, f0.x, a0);
                a1 = fmaf(pk, f0.y, a1);
                a2 = fmaf(pk, f1.x, a2);
                a3 = fmaf(pk, f1.y, a3);
                a4 = fmaf(pk, f2.x, a4);
                a5 = fmaf(pk, f2.y, a5);
                a6 = fmaf(pk, f3.x, a6);
                a7 = fmaf(pk, f3.y, a7);
            }
        }
        if (k < cnt) {
            float pk = __shfl_sync(0xffffffffu, p, k);
            int sk = __shfl_sync(0xffffffffu, s, k);
            if (lane < 12) {
                uint4 hv = __ldg(h16 + (size_t)sk * 12 + cg);
                const __half2* hh = reinterpret_cast<const __half2*>(&hv);
                float2 f0 = __half22float2(hh[0]);
                float2 f1 = __half22float2(hh[1]);
                float2 f2 = __half22float2(hh[2]);
                float2 f3 = __half22float2(hh[3]);
                a0 = fmaf(pk, f0.x, a0);
                a1 = fmaf(pk, f0.y, a1);
                a2 = fmaf(pk, f1.x, a2);
                a3 = fmaf(pk, f1.y, a3);
                a4 = fmaf(pk, f2.x, a4);
                a5 = fmaf(pk, f2.y, a5);
                a6 = fmaf(pk, f3.x, a6);
                a7 = fmaf(pk, f3.y, a7);
            }
        }
    }
    #pragma unroll
    for (int o = 16; o; o >>= 1) psum += __shfl_xor_sync(0xffffffffu, psum, o);

    // combine the two edge-slot halves: lane l (<12) += lane l+12
    float r0 = a0 + __shfl_sync(0xffffffffu, a0, lane + 12);
    float r1 = a1 + __shfl_sync(0xffffffffu, a1, lane + 12);
    float r2 = a2 + __shfl_sync(0xffffffffu, a2, lane + 12);
    float r3 = a3 + __shfl_sync(0xffffffffu, a3, lane + 12);
    float r4 = a4 + __shfl_sync(0xffffffffu, a4, lane + 12);
    float r5 = a5 + __shfl_sync(0xffffffffu, a5, lane + 12);
    float r6 = a6 + __shfl_sync(0xffffffffu, a6, lane + 12);
    float r7 = a7 + __shfl_sync(0xffffffffu, a7, lane + 12);

    float degf = (float)(end - beg);
    float scale = (1.f / fmaxf(psum, 1e-16f)) * (1.f / fmaxf(degf, 1.f));
    if (lane < 12) {
        const float4* b4 = reinterpret_cast<const float4*>(bias);
        float4 bv0 = __ldg(b4 + lane * 2);
        float4 bv1 = __ldg(b4 + lane * 2 + 1);
        float4 o0, o1;
        o0.x = fmaf(r0, scale, bv0.x);
        o0.y = fmaf(r1, scale, bv0.y);
        o0.z = fmaf(r2, scale, bv0.z);
        o0.w = fmaf(r3, scale, bv0.w);
        o1.x = fmaf(r4, scale, bv1.x);
        o1.y = fmaf(r5, scale, bv1.y);
        o1.z = fmaf(r6, scale, bv1.z);
        o1.w = fmaf(r7, scale, bv1.w);
        float4* op = reinterpret_cast<float4*>(outp) + (size_t)gw * 24 + lane * 2;
        op[0] = o0;
        op[1] = o1;
    }
}

// ---------------- flat thirds: reshape(3,N,32).sum(0) over the FLAT [N*96] buffer ----
template <bool RELU>
__global__ void k_thirds(const float* __restrict__ f, float* __restrict__ o, int n4) {
    int i = blockIdx.x * blockDim.x + threadIdx.x;
    if (i >= n4) return;
    const float4* f4 = reinterpret_cast<const float4*>(f);
    float4 a = f4[i], b = f4[i + n4], c = f4[i + 2 * n4];
    float4 r;
    r.x = a.x + b.x + c.x;
    r.y = a.y + b.y + c.y;
    r.z = a.z + b.z + c.z;
    r.w = a.w + b.w + c.w;
    if (RELU) {
        r.x = fmaxf(r.x, 0.f); r.y = fmaxf(r.y, 0.f);
        r.z = fmaxf(r.z, 0.f); r.w = fmaxf(r.w, 0.f);
    }
    reinterpret_cast<float4*>(o)[i] = r;
}

// ---------------- fused flat-thirds -> lin1 -> relu -> lin2 -> sigmoid -------------
__global__ void k_final(const float* __restrict__ t3, const float* __restrict__ Wl1,
                        const float* __restrict__ bl1, const float* __restrict__ Wl2,
                        const float* __restrict__ bl2, float* __restrict__ out, int N) {
    __shared__ float w1s[32 * 96];
    __shared__ float w2s[96 * 32];
    __shared__ float b1s[96];
    __shared__ float b2s[32];
    __shared__ float zs[8][96];
    for (int i = threadIdx.x; i < 3072; i += blockDim.x) {
        w1s[i] = Wl1[i];
        w2s[i] = Wl2[i];
    }
    if (threadIdx.x < 96) b1s[threadIdx.x] = bl1[threadIdx.x];
    if (threadIdx.x < 32) b2s[threadIdx.x] = bl2[threadIdx.x];
    __syncthreads();

    int lane = threadIdx.x & 31;
    int wib = threadIdx.x >> 5;
    int gw = blockIdx.x * 8 + wib;
    int stride = gridDim.x * 8;
    float* zr = zs[wib];
    size_t third = (size_t)N * 32;

    for (int n = gw; n < N; n += stride) {
        size_t idx = (size_t)n * 32 + lane;
        // flat thirds of the layer-2 agg output (no relu per reference)
        float tv = t3[idx] + t3[third + idx] + t3[2 * third + idx];
        float z0 = b1s[lane], z1 = b1s[lane + 32], z2 = b1s[lane + 64];
        #pragma unroll
        for (int j = 0; j < 32; ++j) {
            float tj = __shfl_sync(0xffffffffu, tv, j);
            z0 = fmaf(tj, w1s[j * 96 + lane], z0);
            z1 = fmaf(tj, w1s[j * 96 + lane + 32], z1);
            z2 = fmaf(tj, w1s[j * 96 + lane + 64], z2);
        }
        zr[lane] = fmaxf(z0, 0.f);
        zr[lane + 32] = fmaxf(z1, 0.f);
        zr[lane + 64] = fmaxf(z2, 0.f);
        __syncwarp();
        float y = b2s[lane];
        #pragma unroll 8
        for (int c = 0; c < 96; ++c) y = fmaf(zr[c], w2s[c * 32 + lane], y);
        out[(size_t)n * 32 + lane] = 1.f / (1.f + __expf(-y));
        __syncwarp();
    }
}

// ---------------- launch ----------------
extern "C" void kernel_launch(void* const* d_in, const int* in_sizes, int n_in,
                              void* d_out, int out_size) {
    const float* x   = (const float*)d_in[0];
    const void*  ei  = d_in[1];
    const float* W1  = (const float*)d_in[2];
    const float* as1 = (const float*)d_in[3];
    const float* ad1 = (const float*)d_in[4];
    const float* b1  = (const float*)d_in[5];
    const float* W2  = (const float*)d_in[6];
    const float* as2 = (const float*)d_in[7];
    const float* ad2 = (const float*)d_in[8];
    const float* b2  = (const float*)d_in[9];
    const float* Wl1 = (const float*)d_in[12];
    const float* bl1 = (const float*)d_in[13];
    const float* Wl2 = (const float*)d_in[14];
    const float* bl2 = (const float*)d_in[15];
    float* out = (float*)d_out;

    int N = in_sizes[0] / 128;
    int E = in_sizes[1] / 2;

    float *p_h, *p_out, *p_small;
    uint4* p_h16;
    cudaGetSymbolAddress((void**)&p_h, g_h);
    cudaGetSymbolAddress((void**)&p_h16, g_h16);
    cudaGetSymbolAddress((void**)&p_out, g_out);
    cudaGetSymbolAddress((void**)&p_small, g_small);

    int warpsBlocks = (N * 32 + 255) / 256;
    int G = (N + 1023) / 1024;

    // --- CSR build, with gemm1 at launch #4 (ncu window) ---
    k_probe<<<1, 32>>>((const int*)ei);                              // 1
    k_init_deg<<<(N + 255) / 256, 256>>>(N);                         // 2
    k_count<<<(E + 255) / 256, 256>>>(ei, E, N);                     // 3
    k_gemm96<128><<<(N + 127) / 128, 384>>>(x, W1, p_h, p_h16, N);   // 4 <- ncu window
    k_scan_blocks<<<G, 1024>>>(N);                                   // 5
    k_scan_sums<<<1, 1024>>>(G, N);                                  // 6
    k_scan_add<<<(N + 255) / 256, 256>>>(N);                         // 7
    k_fill<<<(E + N + 255) / 256, 256>>>(ei, E, N);                  // 8

    // --- layer 1 ---
    k_scores<<<warpsBlocks, 256>>>(p_h, as1, ad1, N);
    k_agg<<<warpsBlocks, 256>>>(p_h16, b1, p_out, N);
    k_thirds<true><<<(N * 8 + 255) / 256, 256>>>(p_out, p_small, N * 8);

    // --- layer 2 ---
    k_gemm96<32><<<(N + 127) / 128, 384>>>(p_small, W2, p_h, p_h16, N);
    k_scores<<<warpsBlocks, 256>>>(p_h, as2, ad2, N);
    k_agg<<<warpsBlocks, 256>>>(p_h16, b2, p_out, N);

    // --- fused flat-thirds + MLP tail ---
    k_final<<<1184, 256>>>(p_out, Wl1, bl1, Wl2, bl2, out, N);
}

// round 14
// speedup vs baseline: 1.1848x; 1.1848x over previous
#include <cuda_runtime.h>
#include <cuda_fp16.h>
#include <cstdint>
#include <cstddef>

#define NN 100000
#define EE 1600000
#define TT (EE + NN)

// ---------------- scratch (static device globals; no allocation) ----------------
__device__ float    g_h[(size_t)NN * 96];    // h fp32 (scores input)
__device__ unsigned g_h16[(size_t)NN * 48];  // h fp16 (half2-packed, agg payload)
__device__ float    g_out[(size_t)NN * 96];  // agg output (fp32, flat thirds)
__device__ unsigned g_x16[(size_t)NN * 64];  // x fp16 (gemm1 A)
__device__ unsigned g_s16[(size_t)NN * 16];  // thirds out fp16 (gemm2 A)
__device__ unsigned g_w16a[6144];            // W1 fp16
__device__ unsigned g_w16b[1536];            // W2 fp16
__device__ float    g_es[NN];
__device__ float    g_ed[NN];
__device__ int      g_deg[NN];
__device__ int      g_rowptr[NN + 1];
__device__ int      g_cursor[NN];
__device__ int      g_csr[TT];
__device__ int      g_bsum[1024];
__device__ int      g_is64;

// ---------------- cp.async / mma helpers ----------------
__device__ __forceinline__ void cp16(void* smem_dst, const void* gsrc, int valid_bytes) {
    unsigned sm = (unsigned)__cvta_generic_to_shared(smem_dst);
    asm volatile("cp.async.cg.shared.global [%0], [%1], 16, %2;"
                 :: "r"(sm), "l"(gsrc), "r"(valid_bytes));
}
__device__ __forceinline__ void cp_commit() {
    asm volatile("cp.async.commit_group;" ::: "memory");
}
__device__ __forceinline__ void cp_wait0() {
    asm volatile("cp.async.wait_group 0;" ::: "memory");
}
__device__ __forceinline__ void ldsm4(unsigned* r, unsigned addr) {
    asm volatile("ldmatrix.sync.aligned.m8n8.x4.shared.b16 {%0,%1,%2,%3}, [%4];"
                 : "=r"(r[0]), "=r"(r[1]), "=r"(r[2]), "=r"(r[3]) : "r"(addr));
}
__device__ __forceinline__ void ldsm4t(unsigned* r, unsigned addr) {
    asm volatile("ldmatrix.sync.aligned.m8n8.x4.trans.shared.b16 {%0,%1,%2,%3}, [%4];"
                 : "=r"(r[0]), "=r"(r[1]), "=r"(r[2]), "=r"(r[3]) : "r"(addr));
}
__device__ __forceinline__ void mma16816(float* d, const unsigned* a, const unsigned* b) {
    asm volatile(
        "mma.sync.aligned.m16n8k16.row.col.f32.f16.f16.f32 "
        "{%0,%1,%2,%3}, {%4,%5,%6,%7}, {%8,%9}, {%0,%1,%2,%3};"
        : "+f"(d[0]), "+f"(d[1]), "+f"(d[2]), "+f"(d[3])
        : "r"(a[0]), "r"(a[1]), "r"(a[2]), "r"(a[3]), "r"(b[0]), "r"(b[1]));
}
__device__ __forceinline__ unsigned pack_h2(float a, float b) {
    __half2 h = __floats2half2_rn(a, b);
    return *reinterpret_cast<unsigned*>(&h);
}

// ---------------- edge-index dtype probe ----------------
__global__ void k_probe(const int* __restrict__ ei32) {
    if (threadIdx.x == 0 && blockIdx.x == 0) {
        int acc = 0;
        #pragma unroll 8
        for (int i = 1; i < 512; i += 2) acc |= ei32[i];
        g_is64 = (acc == 0) ? 1 : 0;
    }
}

__device__ __forceinline__ int load_idx(const void* ei, size_t i, int is64, int N) {
    int v = is64 ? (int)((const long long*)ei)[i] : ((const int*)ei)[i];
    v = v < 0 ? 0 : v;
    return v >= N ? N - 1 : v;
}

// ---------------- fp16 converts ----------------
__global__ void k_cvt_w(const float2* __restrict__ W1, const float2* __restrict__ W2) {
    int i = blockIdx.x * blockDim.x + threadIdx.x;
    if (i < 6144) {
        float2 f = __ldg(W1 + i);
        g_w16a[i] = pack_h2(f.x, f.y);
    } else if (i < 7680) {
        float2 f = __ldg(W2 + (i - 6144));
        g_w16b[i - 6144] = pack_h2(f.x, f.y);
    }
}

__global__ void k_cvt_x(const float4* __restrict__ x4, int n) {
    int i = blockIdx.x * blockDim.x + threadIdx.x;
    if (i >= n) return;
    float4 v = __ldg(x4 + i);
    uint2 u;
    u.x = pack_h2(v.x, v.y);
    u.y = pack_h2(v.z, v.w);
    reinterpret_cast<uint2*>(g_x16)[i] = u;
}

// ---------------- CSR construction ----------------
__global__ void k_init_deg(int N) {
    int i = blockIdx.x * blockDim.x + threadIdx.x;
    if (i < N) g_deg[i] = 1;  // self-loop
}

__global__ void k_count(const void* __restrict__ ei, int E, int N) {
    int i = blockIdx.x * blockDim.x + threadIdx.x;
    if (i < E) {
        int d = load_idx(ei, (size_t)E + i, g_is64, N);
        atomicAdd(&g_deg[d], 1);
    }
}

__global__ void k_scan_blocks(int N) {
    __shared__ int ws[32];
    int i = blockIdx.x * 1024 + threadIdx.x;
    int v = (i < N) ? g_deg[i] : 0;
    int x = v;
    int lane = threadIdx.x & 31, wid = threadIdx.x >> 5;
    #pragma unroll
    for (int o = 1; o < 32; o <<= 1) {
        int y = __shfl_up_sync(0xffffffffu, x, o);
        if (lane >= o) x += y;
    }
    if (lane == 31) ws[wid] = x;
    __syncthreads();
    if (wid == 0) {
        int w = ws[lane];
        #pragma unroll
        for (int o = 1; o < 32; o <<= 1) {
            int y = __shfl_up_sync(0xffffffffu, w, o);
            if (lane >= o) w += y;
        }
        ws[lane] = w;
    }
    __syncthreads();
    int excl = x - v + (wid ? ws[wid - 1] : 0);
    if (i < N) g_rowptr[i] = excl;
    if (threadIdx.x == 1023) g_bsum[blockIdx.x] = ws[31];
}

__global__ void k_scan_sums(int G, int N) {
    __shared__ int ws[32];
    int tid = threadIdx.x;
    int v = (tid < G) ? g_bsum[tid] : 0;
    int x = v;
    int lane = tid & 31, wid = tid >> 5;
    #pragma unroll
    for (int o = 1; o < 32; o <<= 1) {
        int y = __shfl_up_sync(0xffffffffu, x, o);
        if (lane >= o) x += y;
    }
    if (lane == 31) ws[wid] = x;
    __syncthreads();
    if (wid == 0) {
        int w = ws[lane];
        #pragma unroll
        for (int o = 1; o < 32; o <<= 1) {
            int y = __shfl_up_sync(0xffffffffu, w, o);
            if (lane >= o) w += y;
        }
        ws[lane] = w;
    }
    __syncthreads();
    int excl = x - v + (wid ? ws[wid - 1] : 0);
    if (tid < G) g_bsum[tid] = excl;
    if (tid == 1023) g_rowptr[N] = ws[31];
}

__global__ void k_scan_add(int N) {
    int i = blockIdx.x * blockDim.x + threadIdx.x;
    if (i < N) {
        int v = g_rowptr[i] + g_bsum[i >> 10];
        g_rowptr[i] = v;
        g_cursor[i] = v;
    }
}

__global__ void k_fill(const void* __restrict__ ei, int E, int N) {
    int i = blockIdx.x * blockDim.x + threadIdx.x;
    int tot = E + N;
    if (i >= tot) return;
    int s, d;
    if (i < E) {
        int is64 = g_is64;
        s = load_idx(ei, i, is64, N);
        d = load_idx(ei, (size_t)E + i, is64, N);
    } else {
        s = i - E;
        d = s;
    }
    int pos = atomicAdd(&g_cursor[d], 1);
    if (pos < TT) g_csr[pos] = s;
}

// ---------------- tensor-core GEMM: C[N,96] = A16[N,K] @ W16[K,96] -----------------
// mma.m16n8k16 fp16->fp32. 256 threads = 8 warps: warp = 32 rows x 48 cols
// (2 m16-tiles x 6 n8-tiles). BK = min(K,64) staged via cp.async.
template <int K>
__global__ __launch_bounds__(256, 2)
void k_gemm16(const __half* __restrict__ A16, const __half* __restrict__ W16,
              float* __restrict__ C, unsigned* __restrict__ h16, int N) {
    constexpr int BK = (K >= 64) ? 64 : K;
    constexpr int NCH = K / BK;
    constexpr int ACH = BK / 8;  // 16B chunks per A row
    __shared__ __align__(16) __half As[128][BK + 8];
    __shared__ __align__(16) __half Ws[BK][104];
    int tid = threadIdx.x;
    int lane = tid & 31, wid = tid >> 5;
    int row0 = blockIdx.x * 128;
    int wr = (wid & 3) * 32;   // warp row offset
    int wc = (wid >> 2) * 48;  // warp col offset

    float d[2][6][4];
    #pragma unroll
    for (int mi = 0; mi < 2; ++mi)
        #pragma unroll
        for (int nj = 0; nj < 6; ++nj)
            #pragma unroll
            for (int q = 0; q < 4; ++q) d[mi][nj][q] = 0.f;

    for (int ch = 0; ch < NCH; ++ch) {
        for (int i = tid; i < 128 * ACH; i += 256) {
            int r = i / ACH, c = i % ACH;
            bool ok = (row0 + r) < N;
            const __half* src = A16 + (ok ? ((size_t)(row0 + r) * K + ch * BK + c * 8) : 0);
            cp16(&As[r][c * 8], src, ok ? 16 : 0);
        }
        for (int i = tid; i < BK * 12; i += 256) {
            int k = i / 12, c = i % 12;
            cp16(&Ws[k][c * 8], W16 + (size_t)(ch * BK + k) * 96 + c * 8, 16);
        }
        cp_commit();
        cp_wait0();
        __syncthreads();

        #pragma unroll
        for (int k0 = 0; k0 < BK; k0 += 16) {
            unsigned a[2][4], b[3][4];
            #pragma unroll
            for (int mi = 0; mi < 2; ++mi)
                ldsm4(a[mi], (unsigned)__cvta_generic_to_shared(
                                 &As[wr + mi * 16 + (lane & 15)][k0 + (lane >> 4) * 8]));
            #pragma unroll
            for (int nj = 0; nj < 3; ++nj)
                ldsm4t(b[nj], (unsigned)__cvta_generic_to_shared(
                                  &Ws[k0 + (lane & 15)][wc + nj * 16 + (lane >> 4) * 8]));
            #pragma unroll
            for (int mi = 0; mi < 2; ++mi)
                #pragma unroll
                for (int nj = 0; nj < 6; ++nj)
                    mma16816(d[mi][nj], a[mi], &b[nj >> 1][(nj & 1) * 2]);
        }
        __syncthreads();
    }

    int groupID = lane >> 2;
    int c0 = (lane & 3) * 2;
    #pragma unroll
    for (int mi = 0; mi < 2; ++mi) {
        int r1 = row0 + wr + mi * 16 + groupID;
        int r2 = r1 + 8;
        #pragma unroll
        for (int nj = 0; nj < 6; ++nj) {
            int col = wc + nj * 8 + c0;
            if (r1 < N) {
                *reinterpret_cast<float2*>(&C[(size_t)r1 * 96 + col]) =
                    make_float2(d[mi][nj][0], d[mi][nj][1]);
                h16[(size_t)r1 * 48 + col / 2] = pack_h2(d[mi][nj][0], d[mi][nj][1]);
            }
            if (r2 < N) {
                *reinterpret_cast<float2*>(&C[(size_t)r2 * 96 + col]) =
                    make_float2(d[mi][nj][2], d[mi][nj][3]);
                h16[(size_t)r2 * 48 + col / 2] = pack_h2(d[mi][nj][2], d[mi][nj][3]);
            }
        }
    }
}

// ---------------- attention scores: es = h@a_s, ed = h@a_d (fp32 h) ----------------
__global__ void k_scores(const float* __restrict__ h, const float* __restrict__ as_,
                         const float* __restrict__ ad_, int N) {
    int gw = (blockIdx.x * blockDim.x + threadIdx.x) >> 5;
    if (gw >= N) return;
    int lane = threadIdx.x & 31;
    const float* hr = h + (size_t)gw * 96;
    float s = 0.f, d = 0.f;
    #pragma unroll
    for (int f = 0; f < 3; ++f) {
        float hv = hr[lane + 32 * f];
        s = fmaf(hv, __ldg(&as_[lane + 32 * f]), s);
        d = fmaf(hv, __ldg(&ad_[lane + 32 * f]), d);
    }
    #pragma unroll
    for (int o = 16; o; o >>= 1) {
        s += __shfl_xor_sync(0xffffffffu, s, o);
        d += __shfl_xor_sync(0xffffffffu, d, o);
    }
    if (lane == 0) { g_es[gw] = s; g_ed[gw] = d; }
}

// ---------------- warp-per-node softmax aggregation, fp16 gather payload -----------
__global__ void k_agg(const uint4* __restrict__ h16, const float* __restrict__ bias,
                      float* __restrict__ outp, int N) {
    int gw = (blockIdx.x * blockDim.x + threadIdx.x) >> 5;
    if (gw >= N) return;
    int lane = threadIdx.x & 31;
    int beg = g_rowptr[gw], end = g_rowptr[gw + 1];
    float edn = g_ed[gw];
    int half = (lane >= 12) ? 1 : 0;
    int cg = lane % 12;

    float a0 = 0.f, a1 = 0.f, a2 = 0.f, a3 = 0.f;
    float a4 = 0.f, a5 = 0.f, a6 = 0.f, a7 = 0.f;
    float psum = 0.f;

    for (int j0 = beg; j0 < end; j0 += 32) {
        int j = j0 + lane;
        int s = 0;
        float p = 0.f;
        if (j < end) {
            s = __ldg(&g_csr[j]);
            float e = __ldg(&g_es[s]) + edn;
            e = (e > 0.f) ? e : 0.2f * e;
            p = __expf(e);
        }
        psum += p;
        int cnt = min(32, end - j0);
        int k = 0;
        #pragma unroll 4
        for (; k + 1 < cnt; k += 2) {
            int idx = k + half;
            float pk = __shfl_sync(0xffffffffu, p, idx);
            int sk = __shfl_sync(0xffffffffu, s, idx);
            if (lane < 24) {
                uint4 hv = __ldg(h16 + (size_t)sk * 12 + cg);
                const __half2* hh = reinterpret_cast<const __half2*>(&hv);
                float2 f0 = __half22float2(hh[0]);
                float2 f1 = __half22float2(hh[1]);
                float2 f2 = __half22float2(hh[2]);
                float2 f3 = __half22float2(hh[3]);
                a0 = fmaf(pk, f0.x, a0);
                a1 = fmaf(pk, f0.y, a1);
                a2 = fmaf(pk, f1.x, a2);
                a3 = fmaf(pk, f1.y, a3);
                a4 = fmaf(pk, f2.x, a4);
                a5 = fmaf(pk, f2.y, a5);
                a6 = fmaf(pk, f3.x, a6);
                a7 = fmaf(pk, f3.y, a7);
            }
        }
        if (k < cnt) {
            float pk = __shfl_sync(0xffffffffu, p, k);
            int sk = __shfl_sync(0xffffffffu, s, k);
            if (lane < 12) {
                uint4 hv = __ldg(h16 + (size_t)sk * 12 + cg);
                const __half2* hh = reinterpret_cast<const __half2*>(&hv);
                float2 f0 = __half22float2(hh[0]);
                float2 f1 = __half22float2(hh[1]);
                float2 f2 = __half22float2(hh[2]);
                float2 f3 = __half22float2(hh[3]);
                a0 = fmaf(pk, f0.x, a0);
                a1 = fmaf(pk, f0.y, a1);
                a2 = fmaf(pk, f1.x, a2);
                a3 = fmaf(pk, f1.y, a3);
                a4 = fmaf(pk, f2.x, a4);
                a5 = fmaf(pk, f2.y, a5);
                a6 = fmaf(pk, f3.x, a6);
                a7 = fmaf(pk, f3.y, a7);
            }
        }
    }
    #pragma unroll
    for (int o = 16; o; o >>= 1) psum += __shfl_xor_sync(0xffffffffu, psum, o);

    float r0 = a0 + __shfl_sync(0xffffffffu, a0, lane + 12);
    float r1 = a1 + __shfl_sync(0xffffffffu, a1, lane + 12);
    float r2 = a2 + __shfl_sync(0xffffffffu, a2, lane + 12);
    float r3 = a3 + __shfl_sync(0xffffffffu, a3, lane + 12);
    float r4 = a4 + __shfl_sync(0xffffffffu, a4, lane + 12);
    float r5 = a5 + __shfl_sync(0xffffffffu, a5, lane + 12);
    float r6 = a6 + __shfl_sync(0xffffffffu, a6, lane + 12);
    float r7 = a7 + __shfl_sync(0xffffffffu, a7, lane + 12);

    float degf = (float)(end - beg);
    float scale = (1.f / fmaxf(psum, 1e-16f)) * (1.f / fmaxf(degf, 1.f));
    if (lane < 12) {
        const float4* b4 = reinterpret_cast<const float4*>(bias);
        float4 bv0 = __ldg(b4 + lane * 2);
        float4 bv1 = __ldg(b4 + lane * 2 + 1);
        float4 o0, o1;
        o0.x = fmaf(r0, scale, bv0.x);
        o0.y = fmaf(r1, scale, bv0.y);
        o0.z = fmaf(r2, scale, bv0.z);
        o0.w = fmaf(r3, scale, bv0.w);
        o1.x = fmaf(r4, scale, bv1.x);
        o1.y = fmaf(r5, scale, bv1.y);
        o1.z = fmaf(r6, scale, bv1.z);
        o1.w = fmaf(r7, scale, bv1.w);
        float4* op = reinterpret_cast<float4*>(outp) + (size_t)gw * 24 + lane * 2;
        op[0] = o0;
        op[1] = o1;
    }
}

// ---------------- flat thirds (relu) -> fp16 for gemm2 ----------------
__global__ void k_thirds16(const float* __restrict__ f, int n4) {
    int i = blockIdx.x * blockDim.x + threadIdx.x;
    if (i >= n4) return;
    const float4* f4 = reinterpret_cast<const float4*>(f);
    float4 a = f4[i], b = f4[i + n4], c = f4[i + 2 * n4];
    float4 r;
    r.x = fmaxf(a.x + b.x + c.x, 0.f);
    r.y = fmaxf(a.y + b.y + c.y, 0.f);
    r.z = fmaxf(a.z + b.z + c.z, 0.f);
    r.w = fmaxf(a.w + b.w + c.w, 0.f);
    uint2 u;
    u.x = pack_h2(r.x, r.y);
    u.y = pack_h2(r.z, r.w);
    reinterpret_cast<uint2*>(g_s16)[i] = u;
}

// ---------------- fused flat-thirds -> lin1 -> relu -> lin2 -> sigmoid -------------
__global__ void k_final(const float* __restrict__ t3, const float* __restrict__ Wl1,
                        const float* __restrict__ bl1, const float* __restrict__ Wl2,
                        const float* __restrict__ bl2, float* __restrict__ out, int N) {
    __shared__ float w1s[32 * 96];
    __shared__ float w2s[96 * 32];
    __shared__ float b1s[96];
    __shared__ float b2s[32];
    __shared__ float zs[8][96];
    for (int i = threadIdx.x; i < 3072; i += blockDim.x) {
        w1s[i] = Wl1[i];
        w2s[i] = Wl2[i];
    }
    if (threadIdx.x < 96) b1s[threadIdx.x] = bl1[threadIdx.x];
    if (threadIdx.x < 32) b2s[threadIdx.x] = bl2[threadIdx.x];
    __syncthreads();

    int lane = threadIdx.x & 31;
    int wib = threadIdx.x >> 5;
    int gw = blockIdx.x * 8 + wib;
    int stride = gridDim.x * 8;
    float* zr = zs[wib];
    size_t third = (size_t)N * 32;

    for (int n = gw; n < N; n += stride) {
        size_t idx = (size_t)n * 32 + lane;
        float tv = t3[idx] + t3[third + idx] + t3[2 * third + idx];
        float z0 = b1s[lane], z1 = b1s[lane + 32], z2 = b1s[lane + 64];
        #pragma unroll
        for (int j = 0; j < 32; ++j) {
            float tj = __shfl_sync(0xffffffffu, tv, j);
            z0 = fmaf(tj, w1s[j * 96 + lane], z0);
            z1 = fmaf(tj, w1s[j * 96 + lane + 32], z1);
            z2 = fmaf(tj, w1s[j * 96 + lane + 64], z2);
        }
        zr[lane] = fmaxf(z0, 0.f);
        zr[lane + 32] = fmaxf(z1, 0.f);
        zr[lane + 64] = fmaxf(z2, 0.f);
        __syncwarp();
        float y = b2s[lane];
        #pragma unroll 8
        for (int c = 0; c < 96; ++c) y = fmaf(zr[c], w2s[c * 32 + lane], y);
        out[(size_t)n * 32 + lane] = 1.f / (1.f + __expf(-y));
        __syncwarp();
    }
}

// ---------------- launch ----------------
extern "C" void kernel_launch(void* const* d_in, const int* in_sizes, int n_in,
                              void* d_out, int out_size) {
    const float* x   = (const float*)d_in[0];
    const void*  ei  = d_in[1];
    const float* W1  = (const float*)d_in[2];
    const float* as1 = (const float*)d_in[3];
    const float* ad1 = (const float*)d_in[4];
    const float* b1  = (const float*)d_in[5];
    const float* W2  = (const float*)d_in[6];
    const float* as2 = (const float*)d_in[7];
    const float* ad2 = (const float*)d_in[8];
    const float* b2  = (const float*)d_in[9];
    const float* Wl1 = (const float*)d_in[12];
    const float* bl1 = (const float*)d_in[13];
    const float* Wl2 = (const float*)d_in[14];
    const float* bl2 = (const float*)d_in[15];
    float* out = (float*)d_out;

    int N = in_sizes[0] / 128;
    int E = in_sizes[1] / 2;

    float *p_h, *p_out;
    unsigned *p_h16, *p_x16, *p_s16, *p_w16a, *p_w16b;
    cudaGetSymbolAddress((void**)&p_h, g_h);
    cudaGetSymbolAddress((void**)&p_h16, g_h16);
    cudaGetSymbolAddress((void**)&p_out, g_out);
    cudaGetSymbolAddress((void**)&p_x16, g_x16);
    cudaGetSymbolAddress((void**)&p_s16, g_s16);
    cudaGetSymbolAddress((void**)&p_w16a, g_w16a);
    cudaGetSymbolAddress((void**)&p_w16b, g_w16b);

    int warpsBlocks = (N * 32 + 255) / 256;
    int G = (N + 1023) / 1024;

    // 1-4: probe, converts, tensor gemm1 (ncu window at #4)
    k_probe<<<1, 32>>>((const int*)ei);
    k_cvt_w<<<30, 256>>>((const float2*)W1, (const float2*)W2);
    k_cvt_x<<<(N * 32 + 255) / 256, 256>>>((const float4*)x, N * 32);
    k_gemm16<128><<<(N + 127) / 128, 256>>>((const __half*)p_x16, (const __half*)p_w16a,
                                            p_h, p_h16, N);

    // 5-10: CSR build
    k_init_deg<<<(N + 255) / 256, 256>>>(N);
    k_count<<<(E + 255) / 256, 256>>>(ei, E, N);
    k_scan_blocks<<<G, 1024>>>(N);
    k_scan_sums<<<1, 1024>>>(G, N);
    k_scan_add<<<(N + 255) / 256, 256>>>(N);
    k_fill<<<(E + N + 255) / 256, 256>>>(ei, E, N);

    // layer 1
    k_scores<<<warpsBlocks, 256>>>(p_h, as1, ad1, N);
    k_agg<<<warpsBlocks, 256>>>((const uint4*)p_h16, b1, p_out, N);
    k_thirds16<<<(N * 8 + 255) / 256, 256>>>(p_out, N * 8);

    // layer 2
    k_gemm16<32><<<(N + 127) / 128, 256>>>((const __half*)p_s16, (const __half*)p_w16b,
                                           p_h, p_h16, N);
    k_scores<<<warpsBlocks, 256>>>(p_h, as2, ad2, N);
    k_agg<<<warpsBlocks, 256>>>((const uint4*)p_h16, b2, p_out, N);

    // fused flat-thirds + MLP tail
    k_final<<<1184, 256>>>(p_out, Wl1, bl1, Wl2, bl2, out, N);
}

// round 15
// speedup vs baseline: 1.2539x; 1.0584x over previous
#include <cuda_runtime.h>
#include <cuda_fp16.h>
#include <cstdint>
#include <cstddef>

#define NN 100000
#define EE 1600000
#define TT (EE + NN)

// ---------------- scratch (static device globals; no allocation) ----------------
__device__ unsigned g_h16[(size_t)NN * 48];  // h fp16 (half2-packed, agg payload)
__device__ float    g_out[(size_t)NN * 96];  // agg output (fp32, flat thirds)
__device__ unsigned g_x16[(size_t)NN * 64];  // x fp16 (gemm1 A)
__device__ unsigned g_s16[(size_t)NN * 16];  // thirds out fp16 (gemm2 A)
__device__ unsigned g_w16a[6144];            // W1 fp16
__device__ unsigned g_w16b[1536];            // W2 fp16
__device__ float    g_es[NN];
__device__ float    g_ed[NN];
__device__ int      g_deg[NN];
__device__ int      g_rowptr[NN + 1];
__device__ int      g_cursor[NN];
__device__ int      g_csr[TT];
__device__ int      g_bsum[1024];
__device__ int      g_is64;

// ---------------- cp.async / mma helpers ----------------
__device__ __forceinline__ void cp16(void* smem_dst, const void* gsrc, int valid_bytes) {
    unsigned sm = (unsigned)__cvta_generic_to_shared(smem_dst);
    asm volatile("cp.async.cg.shared.global [%0], [%1], 16, %2;"
                 :: "r"(sm), "l"(gsrc), "r"(valid_bytes));
}
__device__ __forceinline__ void cp_commit() {
    asm volatile("cp.async.commit_group;" ::: "memory");
}
__device__ __forceinline__ void cp_wait0() {
    asm volatile("cp.async.wait_group 0;" ::: "memory");
}
__device__ __forceinline__ void ldsm4(unsigned* r, unsigned addr) {
    asm volatile("ldmatrix.sync.aligned.m8n8.x4.shared.b16 {%0,%1,%2,%3}, [%4];"
                 : "=r"(r[0]), "=r"(r[1]), "=r"(r[2]), "=r"(r[3]) : "r"(addr));
}
__device__ __forceinline__ void ldsm4t(unsigned* r, unsigned addr) {
    asm volatile("ldmatrix.sync.aligned.m8n8.x4.trans.shared.b16 {%0,%1,%2,%3}, [%4];"
                 : "=r"(r[0]), "=r"(r[1]), "=r"(r[2]), "=r"(r[3]) : "r"(addr));
}
__device__ __forceinline__ void mma16816(float* d, const unsigned* a, const unsigned* b) {
    asm volatile(
        "mma.sync.aligned.m16n8k16.row.col.f32.f16.f16.f32 "
        "{%0,%1,%2,%3}, {%4,%5,%6,%7}, {%8,%9}, {%0,%1,%2,%3};"
        : "+f"(d[0]), "+f"(d[1]), "+f"(d[2]), "+f"(d[3])
        : "r"(a[0]), "r"(a[1]), "r"(a[2]), "r"(a[3]), "r"(b[0]), "r"(b[1]));
}
__device__ __forceinline__ unsigned pack_h2(float a, float b) {
    __half2 h = __floats2half2_rn(a, b);
    return *reinterpret_cast<unsigned*>(&h);
}

// ---------------- edge-index dtype probe ----------------
__global__ void k_probe(const int* __restrict__ ei32) {
    if (threadIdx.x == 0 && blockIdx.x == 0) {
        int acc = 0;
        #pragma unroll 8
        for (int i = 1; i < 512; i += 2) acc |= ei32[i];
        g_is64 = (acc == 0) ? 1 : 0;
    }
}

__device__ __forceinline__ int load_idx(const void* ei, size_t i, int is64, int N) {
    int v = is64 ? (int)((const long long*)ei)[i] : ((const int*)ei)[i];
    v = v < 0 ? 0 : v;
    return v >= N ? N - 1 : v;
}

// ---------------- fp16 converts ----------------
__global__ void k_cvt_w(const float2* __restrict__ W1, const float2* __restrict__ W2) {
    int i = blockIdx.x * blockDim.x + threadIdx.x;
    if (i < 6144) {
        float2 f = __ldg(W1 + i);
        g_w16a[i] = pack_h2(f.x, f.y);
    } else if (i < 7680) {
        float2 f = __ldg(W2 + (i - 6144));
        g_w16b[i - 6144] = pack_h2(f.x, f.y);
    }
}

__global__ void k_cvt_x(const float4* __restrict__ x4, int n) {
    int i = blockIdx.x * blockDim.x + threadIdx.x;
    if (i >= n) return;
    float4 v = __ldg(x4 + i);
    uint2 u;
    u.x = pack_h2(v.x, v.y);
    u.y = pack_h2(v.z, v.w);
    reinterpret_cast<uint2*>(g_x16)[i] = u;
}

// ---------------- CSR construction ----------------
__global__ void k_init_deg(int N) {
    int i = blockIdx.x * blockDim.x + threadIdx.x;
    if (i < N) g_deg[i] = 1;  // self-loop
}

__global__ void k_count(const void* __restrict__ ei, int E, int N) {
    int i = blockIdx.x * blockDim.x + threadIdx.x;
    if (i < E) {
        int d = load_idx(ei, (size_t)E + i, g_is64, N);
        atomicAdd(&g_deg[d], 1);
    }
}

__global__ void k_scan_blocks(int N) {
    __shared__ int ws[32];
    int i = blockIdx.x * 1024 + threadIdx.x;
    int v = (i < N) ? g_deg[i] : 0;
    int x = v;
    int lane = threadIdx.x & 31, wid = threadIdx.x >> 5;
    #pragma unroll
    for (int o = 1; o < 32; o <<= 1) {
        int y = __shfl_up_sync(0xffffffffu, x, o);
        if (lane >= o) x += y;
    }
    if (lane == 31) ws[wid] = x;
    __syncthreads();
    if (wid == 0) {
        int w = ws[lane];
        #pragma unroll
        for (int o = 1; o < 32; o <<= 1) {
            int y = __shfl_up_sync(0xffffffffu, w, o);
            if (lane >= o) w += y;
        }
        ws[lane] = w;
    }
    __syncthreads();
    int excl = x - v + (wid ? ws[wid - 1] : 0);
    if (i < N) g_rowptr[i] = excl;
    if (threadIdx.x == 1023) g_bsum[blockIdx.x] = ws[31];
}

__global__ void k_scan_sums(int G, int N) {
    __shared__ int ws[32];
    int tid = threadIdx.x;
    int v = (tid < G) ? g_bsum[tid] : 0;
    int x = v;
    int lane = tid & 31, wid = tid >> 5;
    #pragma unroll
    for (int o = 1; o < 32; o <<= 1) {
        int y = __shfl_up_sync(0xffffffffu, x, o);
        if (lane >= o) x += y;
    }
    if (lane == 31) ws[wid] = x;
    __syncthreads();
    if (wid == 0) {
        int w = ws[lane];
        #pragma unroll
        for (int o = 1; o < 32; o <<= 1) {
            int y = __shfl_up_sync(0xffffffffu, w, o);
            if (lane >= o) w += y;
        }
        ws[lane] = w;
    }
    __syncthreads();
    int excl = x - v + (wid ? ws[wid - 1] : 0);
    if (tid < G) g_bsum[tid] = excl;
    if (tid == 1023) g_rowptr[N] = ws[31];
}

__global__ void k_scan_add(int N) {
    int i = blockIdx.x * blockDim.x + threadIdx.x;
    if (i < N) {
        int v = g_rowptr[i] + g_bsum[i >> 10];
        g_rowptr[i] = v;
        g_cursor[i] = v;
    }
}

__global__ void k_fill(const void* __restrict__ ei, int E, int N) {
    int i = blockIdx.x * blockDim.x + threadIdx.x;
    int tot = E + N;
    if (i >= tot) return;
    int s, d;
    if (i < E) {
        int is64 = g_is64;
        s = load_idx(ei, i, is64, N);
        d = load_idx(ei, (size_t)E + i, is64, N);
    } else {
        s = i - E;
        d = s;
    }
    int pos = atomicAdd(&g_cursor[d], 1);
    if (pos < TT) g_csr[pos] = s;
}

// ---------------- tensor-core GEMM + fused scores ----------------------------------
// h = A16 @ W16 (mma m16n8k16, fp32 accum). Emits ONLY:
//   h16  : fp16 payload for agg
//   es,ed: per-row dots with a_s/a_d computed from fp32 accumulators (exact path)
// No fp32 h tensor is ever written.
template <int K>
__global__ __launch_bounds__(256, 2)
void k_gemm16(const __half* __restrict__ A16, const __half* __restrict__ W16,
              unsigned* __restrict__ h16, const float* __restrict__ a_s,
              const float* __restrict__ a_d, float* __restrict__ es,
              float* __restrict__ ed, int N) {
    constexpr int BK = (K >= 64) ? 64 : K;
    constexpr int NCH = K / BK;
    constexpr int ACH = BK / 8;  // 16B chunks per A row
    __shared__ __align__(16) __half As[128][BK + 8];
    __shared__ __align__(16) __half Ws[BK][104];
    __shared__ float sdot[128];
    __shared__ float ddot[128];
    int tid = threadIdx.x;
    int lane = tid & 31, wid = tid >> 5;
    int row0 = blockIdx.x * 128;
    int wr = (wid & 3) * 32;   // warp row offset
    int wc = (wid >> 2) * 48;  // warp col offset

    for (int i = tid; i < 128; i += 256) {
        sdot[i] = 0.f;
        ddot[i] = 0.f;
    }

    float d[2][6][4];
    #pragma unroll
    for (int mi = 0; mi < 2; ++mi)
        #pragma unroll
        for (int nj = 0; nj < 6; ++nj)
            #pragma unroll
            for (int q = 0; q < 4; ++q) d[mi][nj][q] = 0.f;

    for (int ch = 0; ch < NCH; ++ch) {
        for (int i = tid; i < 128 * ACH; i += 256) {
            int r = i / ACH, c = i % ACH;
            bool ok = (row0 + r) < N;
            const __half* src = A16 + (ok ? ((size_t)(row0 + r) * K + ch * BK + c * 8) : 0);
            cp16(&As[r][c * 8], src, ok ? 16 : 0);
        }
        for (int i = tid; i < BK * 12; i += 256) {
            int k = i / 12, c = i % 12;
            cp16(&Ws[k][c * 8], W16 + (size_t)(ch * BK + k) * 96 + c * 8, 16);
        }
        cp_commit();
        cp_wait0();
        __syncthreads();

        #pragma unroll
        for (int k0 = 0; k0 < BK; k0 += 16) {
            unsigned a[2][4], b[3][4];
            #pragma unroll
            for (int mi = 0; mi < 2; ++mi)
                ldsm4(a[mi], (unsigned)__cvta_generic_to_shared(
                                 &As[wr + mi * 16 + (lane & 15)][k0 + (lane >> 4) * 8]));
            #pragma unroll
            for (int nj = 0; nj < 3; ++nj)
                ldsm4t(b[nj], (unsigned)__cvta_generic_to_shared(
                                  &Ws[k0 + (lane & 15)][wc + nj * 16 + (lane >> 4) * 8]));
            #pragma unroll
            for (int mi = 0; mi < 2; ++mi)
                #pragma unroll
                for (int nj = 0; nj < 6; ++nj)
                    mma16816(d[mi][nj], a[mi], &b[nj >> 1][(nj & 1) * 2]);
        }
        __syncthreads();
    }

    int groupID = lane >> 2;
    int c0 = (lane & 3) * 2;
    float sa[2][2] = {{0.f, 0.f}, {0.f, 0.f}};  // [mi][r1/r2] dot with a_s
    float da[2][2] = {{0.f, 0.f}, {0.f, 0.f}};  // dot with a_d
    #pragma unroll
    for (int mi = 0; mi < 2; ++mi) {
        int r1 = row0 + wr + mi * 16 + groupID;
        int r2 = r1 + 8;
        #pragma unroll
        for (int nj = 0; nj < 6; ++nj) {
            int col = wc + nj * 8 + c0;
            float as0 = __ldg(&a_s[col]), as1 = __ldg(&a_s[col + 1]);
            float ad0 = __ldg(&a_d[col]), ad1 = __ldg(&a_d[col + 1]);
            sa[mi][0] += d[mi][nj][0] * as0 + d[mi][nj][1] * as1;
            da[mi][0] += d[mi][nj][0] * ad0 + d[mi][nj][1] * ad1;
            sa[mi][1] += d[mi][nj][2] * as0 + d[mi][nj][3] * as1;
            da[mi][1] += d[mi][nj][2] * ad0 + d[mi][nj][3] * ad1;
            if (r1 < N) h16[(size_t)r1 * 48 + col / 2] = pack_h2(d[mi][nj][0], d[mi][nj][1]);
            if (r2 < N) h16[(size_t)r2 * 48 + col / 2] = pack_h2(d[mi][nj][2], d[mi][nj][3]);
        }
        int lr1 = wr + mi * 16 + groupID;
        atomicAdd(&sdot[lr1], sa[mi][0]);
        atomicAdd(&ddot[lr1], da[mi][0]);
        atomicAdd(&sdot[lr1 + 8], sa[mi][1]);
        atomicAdd(&ddot[lr1 + 8], da[mi][1]);
    }
    __syncthreads();
    for (int i = tid; i < 128; i += 256) {
        int r = row0 + i;
        if (r < N) {
            es[r] = sdot[i];
            ed[r] = ddot[i];
        }
    }
}

// ---------------- warp-per-node softmax aggregation, fp16 gather payload -----------
__global__ void k_agg(const uint4* __restrict__ h16, const float* __restrict__ bias,
                      float* __restrict__ outp, int N) {
    int gw = (blockIdx.x * blockDim.x + threadIdx.x) >> 5;
    if (gw >= N) return;
    int lane = threadIdx.x & 31;
    int beg = g_rowptr[gw], end = g_rowptr[gw + 1];
    float edn = g_ed[gw];
    int half = (lane >= 12) ? 1 : 0;
    int cg = lane % 12;

    float a0 = 0.f, a1 = 0.f, a2 = 0.f, a3 = 0.f;
    float a4 = 0.f, a5 = 0.f, a6 = 0.f, a7 = 0.f;
    float psum = 0.f;

    for (int j0 = beg; j0 < end; j0 += 32) {
        int j = j0 + lane;
        int s = 0;
        float p = 0.f;
        if (j < end) {
            s = __ldg(&g_csr[j]);
            float e = __ldg(&g_es[s]) + edn;
            e = (e > 0.f) ? e : 0.2f * e;
            p = __expf(e);
        }
        psum += p;
        int cnt = min(32, end - j0);
        int k = 0;
        #pragma unroll 4
        for (; k + 1 < cnt; k += 2) {
            int idx = k + half;
            float pk = __shfl_sync(0xffffffffu, p, idx);
            int sk = __shfl_sync(0xffffffffu, s, idx);
            if (lane < 24) {
                uint4 hv = __ldg(h16 + (size_t)sk * 12 + cg);
                const __half2* hh = reinterpret_cast<const __half2*>(&hv);
                float2 f0 = __half22float2(hh[0]);
                float2 f1 = __half22float2(hh[1]);
                float2 f2 = __half22float2(hh[2]);
                float2 f3 = __half22float2(hh[3]);
                a0 = fmaf(pk, f0.x, a0);
                a1 = fmaf(pk, f0.y, a1);
                a2 = fmaf(pk, f1.x, a2);
                a3 = fmaf(pk, f1.y, a3);
                a4 = fmaf(pk, f2.x, a4);
                a5 = fmaf(pk, f2.y, a5);
                a6 = fmaf(pk, f3.x, a6);
                a7 = fmaf(pk, f3.y, a7);
            }
        }
        if (k < cnt) {
            float pk = __shfl_sync(0xffffffffu, p, k);
            int sk = __shfl_sync(0xffffffffu, s, k);
            if (lane < 12) {
                uint4 hv = __ldg(h16 + (size_t)sk * 12 + cg);
                const __half2* hh = reinterpret_cast<const __half2*>(&hv);
                float2 f0 = __half22float2(hh[0]);
                float2 f1 = __half22float2(hh[1]);
                float2 f2 = __half22float2(hh[2]);
                float2 f3 = __half22float2(hh[3]);
                a0 = fmaf(pk, f0.x, a0);
                a1 = fmaf(pk, f0.y, a1);
                a2 = fmaf(pk, f1.x, a2);
                a3 = fmaf(pk, f1.y, a3);
                a4 = fmaf(pk, f2.x, a4);
                a5 = fmaf(pk, f2.y, a5);
                a6 = fmaf(pk, f3.x, a6);
                a7 = fmaf(pk, f3.y, a7);
            }
        }
    }
    #pragma unroll
    for (int o = 16; o; o >>= 1) psum += __shfl_xor_sync(0xffffffffu, psum, o);

    float r0 = a0 + __shfl_sync(0xffffffffu, a0, lane + 12);
    float r1 = a1 + __shfl_sync(0xffffffffu, a1, lane + 12);
    float r2 = a2 + __shfl_sync(0xffffffffu, a2, lane + 12);
    float r3 = a3 + __shfl_sync(0xffffffffu, a3, lane + 12);
    float r4 = a4 + __shfl_sync(0xffffffffu, a4, lane + 12);
    float r5 = a5 + __shfl_sync(0xffffffffu, a5, lane + 12);
    float r6 = a6 + __shfl_sync(0xffffffffu, a6, lane + 12);
    float r7 = a7 + __shfl_sync(0xffffffffu, a7, lane + 12);

    float degf = (float)(end - beg);
    float scale = (1.f / fmaxf(psum, 1e-16f)) * (1.f / fmaxf(degf, 1.f));
    if (lane < 12) {
        const float4* b4 = reinterpret_cast<const float4*>(bias);
        float4 bv0 = __ldg(b4 + lane * 2);
        float4 bv1 = __ldg(b4 + lane * 2 + 1);
        float4 o0, o1;
        o0.x = fmaf(r0, scale, bv0.x);
        o0.y = fmaf(r1, scale, bv0.y);
        o0.z = fmaf(r2, scale, bv0.z);
        o0.w = fmaf(r3, scale, bv0.w);
        o1.x = fmaf(r4, scale, bv1.x);
        o1.y = fmaf(r5, scale, bv1.y);
        o1.z = fmaf(r6, scale, bv1.z);
        o1.w = fmaf(r7, scale, bv1.w);
        float4* op = reinterpret_cast<float4*>(outp) + (size_t)gw * 24 + lane * 2;
        op[0] = o0;
        op[1] = o1;
    }
}

// ---------------- flat thirds (relu) -> fp16 for gemm2 ----------------
__global__ void k_thirds16(const float* __restrict__ f, int n4) {
    int i = blockIdx.x * blockDim.x + threadIdx.x;
    if (i >= n4) return;
    const float4* f4 = reinterpret_cast<const float4*>(f);
    float4 a = f4[i], b = f4[i + n4], c = f4[i + 2 * n4];
    float4 r;
    r.x = fmaxf(a.x + b.x + c.x, 0.f);
    r.y = fmaxf(a.y + b.y + c.y, 0.f);
    r.z = fmaxf(a.z + b.z + c.z, 0.f);
    r.w = fmaxf(a.w + b.w + c.w, 0.f);
    uint2 u;
    u.x = pack_h2(r.x, r.y);
    u.y = pack_h2(r.z, r.w);
    reinterpret_cast<uint2*>(g_s16)[i] = u;
}

// ---------------- fused flat-thirds -> lin1 -> relu -> lin2 -> sigmoid -------------
__global__ void k_final(const float* __restrict__ t3, const float* __restrict__ Wl1,
                        const float* __restrict__ bl1, const float* __restrict__ Wl2,
                        const float* __restrict__ bl2, float* __restrict__ out, int N) {
    __shared__ float w1s[32 * 96];
    __shared__ float w2s[96 * 32];
    __shared__ float b1s[96];
    __shared__ float b2s[32];
    __shared__ float zs[8][96];
    for (int i = threadIdx.x; i < 3072; i += blockDim.x) {
        w1s[i] = Wl1[i];
        w2s[i] = Wl2[i];
    }
    if (threadIdx.x < 96) b1s[threadIdx.x] = bl1[threadIdx.x];
    if (threadIdx.x < 32) b2s[threadIdx.x] = bl2[threadIdx.x];
    __syncthreads();

    int lane = threadIdx.x & 31;
    int wib = threadIdx.x >> 5;
    int gw = blockIdx.x * 8 + wib;
    int stride = gridDim.x * 8;
    float* zr = zs[wib];
    size_t third = (size_t)N * 32;

    for (int n = gw; n < N; n += stride) {
        size_t idx = (size_t)n * 32 + lane;
        float tv = t3[idx] + t3[third + idx] + t3[2 * third + idx];
        float z0 = b1s[lane], z1 = b1s[lane + 32], z2 = b1s[lane + 64];
        #pragma unroll
        for (int j = 0; j < 32; ++j) {
            float tj = __shfl_sync(0xffffffffu, tv, j);
            z0 = fmaf(tj, w1s[j * 96 + lane], z0);
            z1 = fmaf(tj, w1s[j * 96 + lane + 32], z1);
            z2 = fmaf(tj, w1s[j * 96 + lane + 64], z2);
        }
        zr[lane] = fmaxf(z0, 0.f);
        zr[lane + 32] = fmaxf(z1, 0.f);
        zr[lane + 64] = fmaxf(z2, 0.f);
        __syncwarp();
        float y = b2s[lane];
        #pragma unroll 8
        for (int c = 0; c < 96; ++c) y = fmaf(zr[c], w2s[c * 32 + lane], y);
        out[(size_t)n * 32 + lane] = 1.f / (1.f + __expf(-y));
        __syncwarp();
    }
}

// ---------------- launch ----------------
extern "C" void kernel_launch(void* const* d_in, const int* in_sizes, int n_in,
                              void* d_out, int out_size) {
    const float* x   = (const float*)d_in[0];
    const void*  ei  = d_in[1];
    const float* W1  = (const float*)d_in[2];
    const float* as1 = (const float*)d_in[3];
    const float* ad1 = (const float*)d_in[4];
    const float* b1  = (const float*)d_in[5];
    const float* W2  = (const float*)d_in[6];
    const float* as2 = (const float*)d_in[7];
    const float* ad2 = (const float*)d_in[8];
    const float* b2  = (const float*)d_in[9];
    const float* Wl1 = (const float*)d_in[12];
    const float* bl1 = (const float*)d_in[13];
    const float* Wl2 = (const float*)d_in[14];
    const float* bl2 = (const float*)d_in[15];
    float* out = (float*)d_out;

    int N = in_sizes[0] / 128;
    int E = in_sizes[1] / 2;

    float *p_out, *p_es, *p_ed;
    unsigned *p_h16, *p_x16, *p_s16, *p_w16a, *p_w16b;
    cudaGetSymbolAddress((void**)&p_h16, g_h16);
    cudaGetSymbolAddress((void**)&p_out, g_out);
    cudaGetSymbolAddress((void**)&p_x16, g_x16);
    cudaGetSymbolAddress((void**)&p_s16, g_s16);
    cudaGetSymbolAddress((void**)&p_w16a, g_w16a);
    cudaGetSymbolAddress((void**)&p_w16b, g_w16b);
    cudaGetSymbolAddress((void**)&p_es, g_es);
    cudaGetSymbolAddress((void**)&p_ed, g_ed);

    int warpsBlocks = (N * 32 + 255) / 256;
    int G = (N + 1023) / 1024;

    // 1-4: probe, converts, tensor gemm1+scores (ncu window at #4)
    k_probe<<<1, 32>>>((const int*)ei);
    k_cvt_w<<<30, 256>>>((const float2*)W1, (const float2*)W2);
    k_cvt_x<<<(N * 32 + 255) / 256, 256>>>((const float4*)x, N * 32);
    k_gemm16<128><<<(N + 127) / 128, 256>>>((const __half*)p_x16, (const __half*)p_w16a,
                                            p_h16, as1, ad1, p_es, p_ed, N);

    // 5-10: CSR build
    k_init_deg<<<(N + 255) / 256, 256>>>(N);
    k_count<<<(E + 255) / 256, 256>>>(ei, E, N);
    k_scan_blocks<<<G, 1024>>>(N);
    k_scan_sums<<<1, 1024>>>(G, N);
    k_scan_add<<<(N + 255) / 256, 256>>>(N);
    k_fill<<<(E + N + 255) / 256, 256>>>(ei, E, N);

    // layer 1
    k_agg<<<warpsBlocks, 256>>>((const uint4*)p_h16, b1, p_out, N);
    k_thirds16<<<(N * 8 + 255) / 256, 256>>>(p_out, N * 8);

    // layer 2 (gemm+scores fused)
    k_gemm16<32><<<(N + 127) / 128, 256>>>((const __half*)p_s16, (const __half*)p_w16b,
                                           p_h16, as2, ad2, p_es, p_ed, N);
    k_agg<<<warpsBlocks, 256>>>((const uint4*)p_h16, b2, p_out, N);

    // fused flat-thirds + MLP tail
    k_final<<<1184, 256>>>(p_out, Wl1, bl1, Wl2, bl2, out, N);
}